// round 10
// baseline (speedup 1.0000x reference)
#include <cuda_runtime.h>
#include <cuda_bf16.h>

// ---------------- problem constants (dataset-fixed) ----------------
#define B_    32
#define H_    32
#define KVH_  8
#define G_    4
#define D_    128
#define SW_   4096
#define HID_  4096
#define QKVD_ 6144
#define POS_  2047          // current_pos (dataset constant)
#define L_    2048          // min(current_pos+1, SW)
#define CH_   32            // keys per attention chunk
#define CPG_  8             // chunks per work item
#define NCHG_ 8             // chunk groups = L/(CH*CPG)
#define NHEAD_ 1024         // B * H
#define NBKV_  256          // B * KVH
#define NITEM_ (NBKV_ * NCHG_)     // 2048 work items
#define PGRID_ 456                 // persistent grid = 152 SM * 3
#define SPLITS_ 16
#define KC_     (HID_ / SPLITS_)   // 256
#define KSTR_   66          // attn K row stride in u64 (16B-aligned, cp16-able)
#define BQ_     (B_ * QKVD_)       // g_part slice stride for QKV

typedef unsigned long long u64;

// ---------------- scratch (no allocations allowed) ----------------
__device__ __align__(16) float g_part[SPLITS_ * B_ * QKVD_];
__device__ __align__(16) float g_q[B_ * H_ * D_];
__device__ __align__(16) float g_knew[B_ * KVH_ * D_];
__device__ __align__(16) float g_vnew[B_ * KVH_ * D_];
__device__ __align__(16) float g_attout[B_ * HID_];
__device__ __align__(16) float g_pml[NCHG_ * NHEAD_ * 2];
__device__ __align__(16) float g_po [NCHG_ * NHEAD_ * D_];

// ---------------- f32x2 / async helpers ----------------
__device__ __forceinline__ u64 pack2(float lo, float hi) {
    u64 r; asm("mov.b64 %0, {%1, %2};" : "=l"(r) : "f"(lo), "f"(hi)); return r;
}
__device__ __forceinline__ void unpack2(u64 v, float& lo, float& hi) {
    asm("mov.b64 {%0, %1}, %2;" : "=f"(lo), "=f"(hi) : "l"(v));
}
__device__ __forceinline__ u64 fma2(u64 a, u64 b, u64 c) {
    u64 d; asm("fma.rn.f32x2 %0, %1, %2, %3;" : "=l"(d) : "l"(a), "l"(b), "l"(c)); return d;
}
__device__ __forceinline__ unsigned su32(const void* p) {
    return (unsigned)__cvta_generic_to_shared(p);
}
__device__ __forceinline__ void cp16(unsigned dst, const void* src) {
    asm volatile("cp.async.cg.shared.global [%0], [%1], 16;" :: "r"(dst), "l"(src));
}
__device__ __forceinline__ void cp_commit() {
    asm volatile("cp.async.commit_group;");
}

// ====================================================================
// Split-K GEMM, cp.async pipelined (4-deep W ring, 2 groups in flight).
// Block = 256 threads, 256 cols (1 per thread), split-K 16.
// X chunk [32 m][256 k] staged once transposed (broadcast LDS.64 reads).
// W streamed as 32 tiles of [8 k][256 j]; inner W read = conflict-free
// LDS.32. 24 warps/SM absorb barrier/LDS latency.
// smem = 256*36*4 + 4*8*256*4 = 69632 B -> 3 blocks/SM.
// ====================================================================
#define GEMM_SMEM_ 69632

__global__ __launch_bounds__(256) void gemm_part(const float* __restrict__ Xin,
                                                 const float* __restrict__ W,
                                                 int N, int use_attout)
{
    extern __shared__ float gsm[];
    float* xs = gsm;                    // [256 k][36] (m in first 32)
    float* WT = gsm + KC_ * 36;         // [4][8][256]

    const float* __restrict__ X = use_attout ? g_attout : Xin;
    const int t  = threadIdx.x;            // 0..255
    const int j0 = blockIdx.x * 256;
    const int j  = j0 + t;
    const int k0 = blockIdx.y * KC_;

    auto issue_tile = [&](int ti) {
        float* dst = WT + (ti & 3) * 8 * 256;
        const float* src = W + (size_t)(k0 + ti * 8) * N + j0;
#pragma unroll
        for (int i = 0; i < 2; i++) {
            int slot = t + 256 * i;          // 0..511
            int r  = slot >> 6;              // 0..7
            int c4 = slot & 63;
            cp16(su32(dst + r * 256 + c4 * 4), src + (size_t)r * N + c4 * 4);
        }
        cp_commit();
    };

    issue_tile(0);
    issue_tile(1);
    issue_tile(2);

    // stage X chunk transposed: 2048 float4 slots, 8/thread
#pragma unroll
    for (int i = 0; i < 8; i++) {
        int slot = t + 256 * i;              // 0..2047
        int m  = slot >> 6;                  // 0..31
        int c4 = slot & 63;                  // 0..63
        const float4 v = *(const float4*)&X[m * HID_ + k0 + c4 * 4];
        xs[(c4 * 4 + 0) * 36 + m] = v.x;
        xs[(c4 * 4 + 1) * 36 + m] = v.y;
        xs[(c4 * 4 + 2) * 36 + m] = v.z;
        xs[(c4 * 4 + 3) * 36 + m] = v.w;
    }

    u64 acc[16];
#pragma unroll
    for (int r = 0; r < 16; r++) acc[r] = 0ULL;

#pragma unroll 1
    for (int ti = 0; ti < 32; ti++) {
        if (ti <= 29)      asm volatile("cp.async.wait_group 2;");
        else if (ti == 30) asm volatile("cp.async.wait_group 1;");
        else               asm volatile("cp.async.wait_group 0;");
        __syncthreads();                      // tile ti visible; tile ti-1 done
        if (ti + 3 < 32) issue_tile(ti + 3);  // reuses tile (ti-1)'s buffer

        const float* wt = WT + (ti & 3) * 8 * 256;
#pragma unroll
        for (int kk = 0; kk < 8; kk++) {
            const float w = wt[kk * 256 + t];           // LDS.32, conflict-free
            const u64 w0 = pack2(w, w);
            const u64* xr = (const u64*)&xs[(ti * 8 + kk) * 36]; // broadcast
#pragma unroll
            for (int r = 0; r < 16; r++)
                acc[r] = fma2(xr[r], w0, acc[r]);
        }
    }

    float* op = g_part + (size_t)blockIdx.y * 32 * N;
#pragma unroll
    for (int r = 0; r < 16; r++) {
        float a, b;
        unpack2(acc[r], a, b);
        op[(size_t)(2 * r) * N + j]     = a;
        op[(size_t)(2 * r + 1) * N + j] = b;
    }
}

// ---------------- split-K reduction (WO output only) ----------------
__global__ void reduce_part(float* __restrict__ outp, int total)
{
    int i = blockIdx.x * 256 + threadIdx.x;
    float a = 0.f;
#pragma unroll
    for (int s = 0; s < SPLITS_; s++) a += g_part[(size_t)s * total + i];
    outp[i] = a;
}

// ====================================================================
// RoPE with fused QKV split-K reduction.
// ====================================================================
__device__ __forceinline__ float part_sum(int idx)
{
    float a = 0.f;
#pragma unroll
    for (int s = 0; s < SPLITS_; s++) a += g_part[(size_t)s * BQ_ + idx];
    return a;
}

__global__ void rope_kernel(const float* __restrict__ rot)
{
    __shared__ float xr[128];
    const int t   = threadIdx.x;
    const int blk = blockIdx.x;

    if (blk < 1024) {
        int b = blk >> 5, h = blk & 31;
        xr[t] = part_sum(b * QKVD_ + h * 128 + t);
        __syncthreads();
        float acc = 0.f;
#pragma unroll 8
        for (int d = 0; d < 128; d++)
            acc = fmaf(xr[d], rot[d * 128 + t], acc);
        g_q[blk * 128 + t] = acc * 0.08838834764831845f;   // D^-0.5
    } else {
        int kv = blk - 1024;
        int b = kv >> 3, kvh = kv & 7;
        xr[t] = part_sum(b * QKVD_ + 4096 + kvh * 128 + t);
        g_vnew[kv * 128 + t] = part_sum(b * QKVD_ + 5120 + kvh * 128 + t);
        __syncthreads();
        float acc = 0.f;
#pragma unroll 8
        for (int d = 0; d < 128; d++)
            acc = fmaf(xr[d], rot[d * 128 + t], acc);
        g_knew[kv * 128 + t] = acc;
    }
}

// ====================================================================
// PERSISTENT pipelined flash-decode attention.
// 456 blocks (3/SM); each walks work items (bkv, grp) with stride 456.
// The cp.async double-buffer ring runs continuously ACROSS item
// boundaries: chunk 0 of the next item is issued while the current
// item's last chunk computes, and the epilogue + q reload + M/L reset
// overlap that in-flight load. Ordering: the reset/q-write happen
// before this thread's next chunk-0 __syncthreads; all readers of
// Msm/Lsm/qs sit after that barrier.
// ====================================================================
#define ATT_SMEM_ (33792 + 32768 + 2048 + 4096 + 512 + 64)

__global__ __launch_bounds__(256) void attn_persist(const float* __restrict__ cache_k,
                                                    const float* __restrict__ cache_v)
{
    extern __shared__ char smem_raw[];
    u64*    kbuf  = (u64*)smem_raw;                  // [2][32*66]
    u64*    vbuf  = kbuf + 2 * 32 * KSTR_;           // [2][32*64]
    float4* qs    = (float4*)(vbuf + 2 * 32 * 64);   // [4*32]
    float*  ss    = (float*)(qs + 128);              // [8dc][4g][32p]
    float*  probs = ss + 1024;                       // [4g][32p]
    float*  Msm   = probs + 128;                     // [4]
    float*  Lsm   = Msm + 4;                         // [4]
    float*  Asm   = Lsm + 4;                         // [4] alpha

    const int t = threadIdx.x;         // 0..255
    const int pvg  = t >> 6;
    const int pvd2 = t & 63;

    auto issue_chunk = [&](int item, int cc, int buf) {
        const int bkv = item & (NBKV_ - 1);
        const int p0  = ((item >> 8) * CPG_ + cc) * CH_;
        u64* kb = kbuf + buf * 32 * KSTR_;
        u64* vb = vbuf + buf * 32 * 64;
#pragma unroll
        for (int i = 0; i < 4; i++) {
            int slot = t + 256 * i;            // 0..1023
            int p = slot >> 5, dq = slot & 31;
            int gp = p0 + p;
            const float* ks = (gp == POS_)
                ? (g_knew + bkv * D_)
                : (cache_k + ((size_t)bkv * SW_ + gp) * D_);
            cp16(su32(kb + p * KSTR_ + dq * 2), ks + dq * 4);
        }
#pragma unroll
        for (int i = 0; i < 4; i++) {
            int slot = t + 256 * i;
            int p = slot >> 5, dq = slot & 31;
            int gp = p0 + p;
            const float* vs = (gp == POS_)
                ? (g_vnew + bkv * D_)
                : (cache_v + ((size_t)bkv * SW_ + gp) * D_);
            cp16(su32(vb + p * 64 + dq * 2), vs + dq * 4);
        }
        cp_commit();
    };

    auto load_q = [&](int item) {
        if (t < 128) {
            int bkv = item & (NBKV_ - 1);
            int g = t >> 5, dq = t & 31;
            qs[g * 32 + dq] = *(const float4*)&g_q[(bkv * 4 + g) * 128 + dq * 4];
        }
        if (t < 4) { Msm[t] = -1e30f; Lsm[t] = 0.f; }
    };

    int it = blockIdx.x;
    load_q(it);
    issue_chunk(it, 0, 0);
    int buf = 0;
    u64 O = 0ULL;

#pragma unroll 1
    for (; it < NITEM_; it += PGRID_) {
#pragma unroll 1
        for (int cc = 0; cc < CPG_; cc++) {
            // issue the next chunk in the GLOBAL sequence
            if (cc < CPG_ - 1) {
                issue_chunk(it, cc + 1, buf ^ 1);
                asm volatile("cp.async.wait_group 1;");
            } else if (it + PGRID_ < NITEM_) {
                issue_chunk(it + PGRID_, 0, buf ^ 1);
                asm volatile("cp.async.wait_group 1;");
            } else {
                asm volatile("cp.async.wait_group 0;");
            }
            __syncthreads();

            const u64* kb = kbuf + buf * 32 * KSTR_;
            const u64* vb = vbuf + buf * 32 * 64;

            // scores: thread = (p = t&31, dc = t>>5 of 8); 16 d each
            {
                int p = t & 31, dc = t >> 5;
                const u64* kp = kb + p * KSTR_ + dc * 8;
                const u64* q2 = (const u64*)qs;
                u64 a0 = 0ULL, a1 = 0ULL, a2 = 0ULL, a3 = 0ULL;
#pragma unroll
                for (int i = 0; i < 8; i++) {
                    u64 k2 = kp[i];
                    int qi = dc * 8 + i;
                    a0 = fma2(k2, q2[qi],       a0);
                    a1 = fma2(k2, q2[64 + qi],  a1);
                    a2 = fma2(k2, q2[128 + qi], a2);
                    a3 = fma2(k2, q2[192 + qi], a3);
                }
                float lo, hi;
                unpack2(a0, lo, hi); ss[(dc * 4 + 0) * 32 + p] = lo + hi;
                unpack2(a1, lo, hi); ss[(dc * 4 + 1) * 32 + p] = lo + hi;
                unpack2(a2, lo, hi); ss[(dc * 4 + 2) * 32 + p] = lo + hi;
                unpack2(a3, lo, hi); ss[(dc * 4 + 3) * 32 + p] = lo + hi;
            }
            __syncthreads();

            // d-chunk sum + online softmax: warp g (t<128)
            if (t < 128) {
                int g = t >> 5, p = t & 31;
                float s = 0.f;
#pragma unroll
                for (int dc = 0; dc < 8; dc++)
                    s += ss[(dc * 4 + g) * 32 + p];

                float mc = s;
#pragma unroll
                for (int o = 16; o > 0; o >>= 1)
                    mc = fmaxf(mc, __shfl_xor_sync(0xffffffffu, mc, o));
                float Mold = Msm[g];
                float Mnew = fmaxf(Mold, mc);
                float e = __expf(s - Mnew);
                probs[g * 32 + p] = e;
                float l = e;
#pragma unroll
                for (int o = 16; o > 0; o >>= 1)
                    l += __shfl_xor_sync(0xffffffffu, l, o);
                if (p == 0) {
                    float alpha = __expf(Mold - Mnew);
                    Asm[g] = alpha;
                    Lsm[g] = Lsm[g] * alpha + l;
                    Msm[g] = Mnew;
                }
            }
            __syncthreads();

            // pv with online rescale: thread = (g = t>>6, d2 = t&63)
            {
                float alpha = Asm[pvg];
                O = fma2(O, pack2(alpha, alpha), 0ULL);
                const float* pr = probs + pvg * 32;
#pragma unroll
                for (int p = 0; p < 32; p++) {
                    float w = pr[p];
                    O = fma2(vb[p * 64 + pvd2], pack2(w, w), O);
                }
            }
            __syncthreads();
            buf ^= 1;
        }

        // ---- epilogue for item `it` (overlaps next item's chunk-0 load) ----
        {
            const int bkv = it & (NBKV_ - 1);
            const int grp = it >> 8;
            int head = bkv * 4 + pvg;
            float o0, o1;
            unpack2(O, o0, o1);
            *(float2*)&g_po[((size_t)grp * NHEAD_ + head) * D_ + pvd2 * 2] =
                make_float2(o0, o1);
            if (t < 4) {
                int h4 = bkv * 4 + t;
                g_pml[(grp * NHEAD_ + h4) * 2 + 0] = Msm[t];
                g_pml[(grp * NHEAD_ + h4) * 2 + 1] = Lsm[t];
            }
        }
        O = 0ULL;
        if (it + PGRID_ < NITEM_) load_q(it + PGRID_);  // also resets Msm/Lsm
    }
}

// ---------------- combine per-group softmax partials ----------------
__global__ void combine_kernel()
{
    const int head = blockIdx.x;
    const int t    = threadIdx.x;

    float M = -1e30f;
#pragma unroll
    for (int c = 0; c < NCHG_; c++)
        M = fmaxf(M, g_pml[(c * NHEAD_ + head) * 2]);

    float denom = 0.f, acc = 0.f;
#pragma unroll
    for (int c = 0; c < NCHG_; c++) {
        float m = g_pml[(c * NHEAD_ + head) * 2 + 0];
        float l = g_pml[(c * NHEAD_ + head) * 2 + 1];
        float w = __expf(m - M);
        denom += w * l;
        acc = fmaf(w, g_po[((size_t)c * NHEAD_ + head) * D_ + t], acc);
    }
    g_attout[head * 128 + t] = acc / denom;
}

// ====================================================================
extern "C" void kernel_launch(void* const* d_in, const int* in_sizes, int n_in,
                              void* d_out, int out_size)
{
    const float* x    = (const float*)d_in[0];
    const float* wqkv = (const float*)d_in[1];
    const float* wo   = (const float*)d_in[2];
    const float* rot  = (const float*)d_in[3];
    const float* ck   = (const float*)d_in[4];
    const float* cv   = (const float*)d_in[5];
    float* out = (float*)d_out;

    static int smem_set = 0;
    if (!smem_set) {
        cudaFuncSetAttribute(attn_persist,
                             cudaFuncAttributeMaxDynamicSharedMemorySize,
                             ATT_SMEM_);
        cudaFuncSetAttribute(gemm_part,
                             cudaFuncAttributeMaxDynamicSharedMemorySize,
                             GEMM_SMEM_);
        smem_set = 1;
    }

    // 1) QKV projection (split-K 16, pipelined)
    gemm_part<<<dim3(24, SPLITS_), 256, GEMM_SMEM_>>>(x, wqkv, QKVD_, 0);

    // 2) RoPE with fused split-K reduction
    rope_kernel<<<1280, 128>>>(rot);

    // 3) persistent pipelined flash-decode attention
    attn_persist<<<PGRID_, 256, ATT_SMEM_>>>(ck, cv);
    combine_kernel<<<NHEAD_, 128>>>();

    // 4) output projection (pipelined) + reduce into d_out
    gemm_part<<<dim3(16, SPLITS_), 256, GEMM_SMEM_>>>(nullptr, wo, HID_, 1);
    reduce_part<<<512, 256>>>(out, B_ * HID_);
}

// round 16
// speedup vs baseline: 1.3940x; 1.3940x over previous
#include <cuda_runtime.h>
#include <cuda_bf16.h>
#include <cstdint>

// ---------------- problem constants (dataset-fixed) ----------------
#define B_    32
#define H_    32
#define KVH_  8
#define G_    4
#define D_    128
#define SW_   4096
#define HID_  4096
#define QKVD_ 6144
#define POS_  2047          // current_pos (dataset constant)
#define L_    2048          // min(current_pos+1, SW)
#define CH_   32            // keys per attention chunk
#define CPG_  8             // chunks per work group
#define NCHG_ 8             // chunk groups = L/(CH*CPG)
#define NHEAD_ 1024         // B * H
#define NBKV_  256          // B * KVH
#define SPLITS_ 8
#define KSTR_   66          // attn K row stride in u64
#define BQ_     (B_ * QKVD_)

typedef unsigned long long u64;

// ---------------- scratch (no allocations allowed) ----------------
__device__ __align__(16) float g_part[SPLITS_ * B_ * QKVD_];
__device__ __align__(16) float g_q[B_ * H_ * D_];
__device__ __align__(16) float g_knew[B_ * KVH_ * D_];
__device__ __align__(16) float g_vnew[B_ * KVH_ * D_];
__device__ __align__(16) float g_pml[NCHG_ * NHEAD_ * 2];
__device__ __align__(16) float g_po [NCHG_ * NHEAD_ * D_];
// bf16 hi/lo decompositions of GEMM activations (X for QKV, attout for WO)
__device__ __align__(16) unsigned short g_xhi[B_ * HID_];
__device__ __align__(16) unsigned short g_xlo[B_ * HID_];
__device__ __align__(16) unsigned short g_ahi[B_ * HID_];
__device__ __align__(16) unsigned short g_alo[B_ * HID_];

// ---------------- helpers ----------------
__device__ __forceinline__ u64 pack2(float lo, float hi) {
    u64 r; asm("mov.b64 %0, {%1, %2};" : "=l"(r) : "f"(lo), "f"(hi)); return r;
}
__device__ __forceinline__ void unpack2(u64 v, float& lo, float& hi) {
    asm("mov.b64 {%0, %1}, %2;" : "=f"(lo), "=f"(hi) : "l"(v));
}
__device__ __forceinline__ u64 fma2(u64 a, u64 b, u64 c) {
    u64 d; asm("fma.rn.f32x2 %0, %1, %2, %3;" : "=l"(d) : "l"(a), "l"(b), "l"(c)); return d;
}
__device__ __forceinline__ unsigned su32(const void* p) {
    return (unsigned)__cvta_generic_to_shared(p);
}
__device__ __forceinline__ void cp16(unsigned dst, const void* src) {
    asm volatile("cp.async.cg.shared.global [%0], [%1], 16;" :: "r"(dst), "l"(src));
}
__device__ __forceinline__ void cp_commit() {
    asm volatile("cp.async.commit_group;");
}

// pack two f32 -> bf16x2 {lo=f0, hi=f1}
__device__ __forceinline__ unsigned cvt2(float f0, float f1) {
    unsigned h;
    asm("cvt.rn.bf16x2.f32 %0, %1, %2;" : "=r"(h) : "f"(f1), "f"(f0));
    return h;
}

// m16n8k16 row.col bf16 -> f32 accumulate
__device__ __forceinline__ void mma16816(float* c, const unsigned* a,
                                         unsigned b0, unsigned b1) {
    asm volatile(
        "mma.sync.aligned.m16n8k16.row.col.f32.bf16.bf16.f32 "
        "{%0,%1,%2,%3}, {%4,%5,%6,%7}, {%8,%9}, {%0,%1,%2,%3};"
        : "+f"(c[0]), "+f"(c[1]), "+f"(c[2]), "+f"(c[3])
        : "r"(a[0]), "r"(a[1]), "r"(a[2]), "r"(a[3]), "r"(b0), "r"(b1));
}

// ====================================================================
// convx: X fp32 -> bf16 hi/lo global arrays (one-time, 131072 elems)
// ====================================================================
__global__ void convx(const float* __restrict__ x)
{
    int i = blockIdx.x * 256 + threadIdx.x;
    float f = x[i];
    __nv_bfloat16 h = __float2bfloat16(f);
    g_xhi[i] = __bfloat16_as_ushort(h);
    g_xlo[i] = __bfloat16_as_ushort(__float2bfloat16(f - __bfloat162float(h)));
}

// ====================================================================
// Tensor-core (mma.sync bf16) split-K GEMM:
// D[j][m] = sum_k W[k][j] * X[m][k], 3-pass bf16 hi/lo decomposition,
// fp32 accumulators.
// Block: 256 thr = 8 warps; j-tile 128 (16 j per warp), m = 32
// (4 n-tiles of 8). Split-K 8: chunk 512 k = 16 cp.async double-
// buffered stages of 32 k.
// W staged raw fp32 at 132-float row stride (fragment LDS conflict-
// free); converted to bf16 hi/lo IN REGISTERS at fragment load.
// X staged from prepacked global bf16 hi/lo at 40-bf16 row stride.
// smem = 2*16896 + 2*2560 + 2*2560 = 44032 B.
// ====================================================================
#define GS_WSTRIDE 132
#define GS_WSTAGE  16896          // 32 rows * 528 B
#define OFF_XH     33792
#define OFF_XL     38912
#define GSMEM_     44032

__global__ __launch_bounds__(256) void gemm_mma(const float* __restrict__ W,
                                                int N, int use_att)
{
    extern __shared__ char sm[];
    const unsigned short* __restrict__ xg_h = use_att ? g_ahi : g_xhi;
    const unsigned short* __restrict__ xg_l = use_att ? g_alo : g_xlo;
    const int t    = threadIdx.x;
    const int lane = t & 31, wrp = t >> 5;
    const int gid  = lane >> 2, tid = lane & 3;
    const int j0   = blockIdx.x * 128;
    const int k0   = blockIdx.y * 512;
    const int wj   = wrp * 16;
    const unsigned sb = su32(sm);

    auto issue = [&](int s, int buf) {
        unsigned dw = sb + buf * GS_WSTAGE;
        const float* srcw = W + (size_t)(k0 + s * 32) * N + j0;
#pragma unroll
        for (int r = 0; r < 4; r++) {
            int slot = t + 256 * r;        // 0..1023
            int k = slot >> 5, j4 = slot & 31;
            cp16(dw + k * 528 + j4 * 16, srcw + (size_t)k * N + j4 * 4);
        }
        if (t < 128) {
            int m = t >> 2, c = t & 3;
            const unsigned short* sh = xg_h + m * HID_ + k0 + s * 32 + c * 8;
            const unsigned short* sl = xg_l + m * HID_ + k0 + s * 32 + c * 8;
            cp16(sb + OFF_XH + buf * 2560 + m * 80 + c * 16, sh);
            cp16(sb + OFF_XL + buf * 2560 + m * 80 + c * 16, sl);
        }
        cp_commit();
    };

    float acc[4][4];
#pragma unroll
    for (int nt = 0; nt < 4; nt++)
#pragma unroll
        for (int i = 0; i < 4; i++) acc[nt][i] = 0.f;

    issue(0, 0);

#pragma unroll 1
    for (int s = 0; s < 16; s++) {
        const int buf = s & 1;
        if (s < 15) {
            issue(s + 1, buf ^ 1);
            asm volatile("cp.async.wait_group 1;");
        } else {
            asm volatile("cp.async.wait_group 0;");
        }
        __syncthreads();

        const float* wr = (const float*)(sm + buf * GS_WSTAGE);
        const unsigned short* xh = (const unsigned short*)(sm + OFF_XH + buf * 2560);
        const unsigned short* xl = (const unsigned short*)(sm + OFF_XL + buf * 2560);

#pragma unroll
        for (int ks = 0; ks < 2; ks++) {
            const int kb = ks * 16 + 2 * tid;
            unsigned ah[4], al[4];
#pragma unroll
            for (int i = 0; i < 4; i++) {
                int kk = kb + ((i & 2) ? 8 : 0);
                int jj = wj + gid + ((i & 1) ? 8 : 0);
                float f0 = wr[kk * GS_WSTRIDE + jj];
                float f1 = wr[(kk + 1) * GS_WSTRIDE + jj];
                unsigned h = cvt2(f0, f1);
                float h0 = __uint_as_float(h << 16);
                float h1 = __uint_as_float(h & 0xffff0000u);
                ah[i] = h;
                al[i] = cvt2(f0 - h0, f1 - h1);
            }
            const int kkw = ks * 16 + 2 * tid;
#pragma unroll
            for (int nt = 0; nt < 4; nt++) {
                int m = nt * 8 + gid;
                unsigned bh0 = *(const unsigned*)(xh + m * 40 + kkw);
                unsigned bh1 = *(const unsigned*)(xh + m * 40 + kkw + 8);
                unsigned bl0 = *(const unsigned*)(xl + m * 40 + kkw);
                unsigned bl1 = *(const unsigned*)(xl + m * 40 + kkw + 8);
                mma16816(acc[nt], ah, bh0, bh1);
                mma16816(acc[nt], ah, bl0, bl1);
                mma16816(acc[nt], al, bh0, bh1);
            }
        }
        __syncthreads();
    }

    // epilogue: C frag (row=gid -> j, col=2*tid -> m)
    float* op = g_part + (size_t)blockIdx.y * 32 * N + j0;
#pragma unroll
    for (int nt = 0; nt < 4; nt++) {
        int m = nt * 8 + 2 * tid;
        int j = wj + gid;
        op[(size_t)m * N + j]           = acc[nt][0];
        op[(size_t)(m + 1) * N + j]     = acc[nt][1];
        op[(size_t)m * N + j + 8]       = acc[nt][2];
        op[(size_t)(m + 1) * N + j + 8] = acc[nt][3];
    }
}

// ---------------- split-K reduction (WO output only) ----------------
__global__ void reduce_part(float* __restrict__ outp, int total)
{
    int i = blockIdx.x * 256 + threadIdx.x;
    float a = 0.f;
#pragma unroll
    for (int s = 0; s < SPLITS_; s++) a += g_part[(size_t)s * total + i];
    outp[i] = a;
}

// ====================================================================
// RoPE with fused QKV split-K reduction.
// ====================================================================
__device__ __forceinline__ float part_sum(int idx)
{
    float a = 0.f;
#pragma unroll
    for (int s = 0; s < SPLITS_; s++) a += g_part[(size_t)s * BQ_ + idx];
    return a;
}

__global__ void rope_kernel(const float* __restrict__ rot)
{
    __shared__ float xr[128];
    const int t   = threadIdx.x;
    const int blk = blockIdx.x;

    if (blk < 1024) {
        int b = blk >> 5, h = blk & 31;
        xr[t] = part_sum(b * QKVD_ + h * 128 + t);
        __syncthreads();
        float acc = 0.f;
#pragma unroll 8
        for (int d = 0; d < 128; d++)
            acc = fmaf(xr[d], rot[d * 128 + t], acc);
        g_q[blk * 128 + t] = acc * 0.08838834764831845f;   // D^-0.5
    } else {
        int kv = blk - 1024;
        int b = kv >> 3, kvh = kv & 7;
        xr[t] = part_sum(b * QKVD_ + 4096 + kvh * 128 + t);
        g_vnew[kv * 128 + t] = part_sum(b * QKVD_ + 5120 + kvh * 128 + t);
        __syncthreads();
        float acc = 0.f;
#pragma unroll 8
        for (int d = 0; d < 128; d++)
            acc = fmaf(xr[d], rot[d * 128 + t], acc);
        g_knew[kv * 128 + t] = acc;
    }
}

// ====================================================================
// Pipelined flash-decode attention (proven R9 version, unchanged).
// ====================================================================
#define ATT_SMEM_ (33792 + 32768 + 2048 + 4096 + 512 + 64)

__global__ __launch_bounds__(256) void attn_group(const float* __restrict__ cache_k,
                                                  const float* __restrict__ cache_v)
{
    extern __shared__ char smem_raw[];
    u64*    kbuf  = (u64*)smem_raw;                  // [2][32*66]
    u64*    vbuf  = kbuf + 2 * 32 * KSTR_;           // [2][32*64]
    float4* qs    = (float4*)(vbuf + 2 * 32 * 64);   // [4*32]
    float*  ss    = (float*)(qs + 128);              // [8dc][4g][32p]
    float*  probs = ss + 1024;                       // [4g][32p]
    float*  Msm   = probs + 128;                     // [4]
    float*  Lsm   = Msm + 4;                         // [4]
    float*  Asm   = Lsm + 4;                         // [4] alpha

    const int t   = threadIdx.x;       // 0..255
    const int bkv = blockIdx.x;        // b*8 + kvh
    const int grp = blockIdx.y;        // chunk group
    const int c0  = grp * CPG_;

    if (t < 128) {
        int g = t >> 5, dq = t & 31;
        qs[g * 32 + dq] = *(const float4*)&g_q[(bkv * 4 + g) * 128 + dq * 4];
    }
    if (t < 4) { Msm[t] = -1e30f; Lsm[t] = 0.f; }

    auto issue_chunk = [&](int cc, int buf) {
        const int p0 = (c0 + cc) * CH_;
        u64* kb = kbuf + buf * 32 * KSTR_;
        u64* vb = vbuf + buf * 32 * 64;
#pragma unroll
        for (int i = 0; i < 4; i++) {
            int slot = t + 256 * i;
            int p = slot >> 5, dq = slot & 31;
            int gp = p0 + p;
            const float* ks = (gp == POS_)
                ? (g_knew + bkv * D_)
                : (cache_k + ((size_t)bkv * SW_ + gp) * D_);
            cp16(su32(kb + p * KSTR_ + dq * 2), ks + dq * 4);
        }
#pragma unroll
        for (int i = 0; i < 4; i++) {
            int slot = t + 256 * i;
            int p = slot >> 5, dq = slot & 31;
            int gp = p0 + p;
            const float* vs = (gp == POS_)
                ? (g_vnew + bkv * D_)
                : (cache_v + ((size_t)bkv * SW_ + gp) * D_);
            cp16(su32(vb + p * 64 + dq * 2), vs + dq * 4);
        }
        cp_commit();
    };

    issue_chunk(0, 0);

    u64 O = 0ULL;
    const int pvg  = t >> 6;
    const int pvd2 = t & 63;

#pragma unroll 1
    for (int cc = 0; cc < CPG_; cc++) {
        const int buf = cc & 1;
        if (cc < CPG_ - 1) {
            issue_chunk(cc + 1, buf ^ 1);
            asm volatile("cp.async.wait_group 1;");
        } else {
            asm volatile("cp.async.wait_group 0;");
        }
        __syncthreads();

        const u64* kb = kbuf + buf * 32 * KSTR_;
        const u64* vb = vbuf + buf * 32 * 64;

        {
            int p = t & 31, dc = t >> 5;
            const u64* kp = kb + p * KSTR_ + dc * 8;
            const u64* q2 = (const u64*)qs;
            u64 a0 = 0ULL, a1 = 0ULL, a2 = 0ULL, a3 = 0ULL;
#pragma unroll
            for (int i = 0; i < 8; i++) {
                u64 k2 = kp[i];
                int qi = dc * 8 + i;
                a0 = fma2(k2, q2[qi],       a0);
                a1 = fma2(k2, q2[64 + qi],  a1);
                a2 = fma2(k2, q2[128 + qi], a2);
                a3 = fma2(k2, q2[192 + qi], a3);
            }
            float lo, hi;
            unpack2(a0, lo, hi); ss[(dc * 4 + 0) * 32 + p] = lo + hi;
            unpack2(a1, lo, hi); ss[(dc * 4 + 1) * 32 + p] = lo + hi;
            unpack2(a2, lo, hi); ss[(dc * 4 + 2) * 32 + p] = lo + hi;
            unpack2(a3, lo, hi); ss[(dc * 4 + 3) * 32 + p] = lo + hi;
        }
        __syncthreads();

        if (t < 128) {
            int g = t >> 5, p = t & 31;
            float s = 0.f;
#pragma unroll
            for (int dc = 0; dc < 8; dc++)
                s += ss[(dc * 4 + g) * 32 + p];

            float mc = s;
#pragma unroll
            for (int o = 16; o > 0; o >>= 1)
                mc = fmaxf(mc, __shfl_xor_sync(0xffffffffu, mc, o));
            float Mold = Msm[g];
            float Mnew = fmaxf(Mold, mc);
            float e = __expf(s - Mnew);
            probs[g * 32 + p] = e;
            float l = e;
#pragma unroll
            for (int o = 16; o > 0; o >>= 1)
                l += __shfl_xor_sync(0xffffffffu, l, o);
            if (p == 0) {
                float alpha = __expf(Mold - Mnew);
                Asm[g] = alpha;
                Lsm[g] = Lsm[g] * alpha + l;
                Msm[g] = Mnew;
            }
        }
        __syncthreads();

        {
            float alpha = Asm[pvg];
            O = fma2(O, pack2(alpha, alpha), 0ULL);
            const float* pr = probs + pvg * 32;
#pragma unroll
            for (int p = 0; p < 32; p++) {
                float w = pr[p];
                O = fma2(vb[p * 64 + pvd2], pack2(w, w), O);
            }
        }
        __syncthreads();
    }

    {
        int head = bkv * 4 + pvg;
        float o0, o1;
        unpack2(O, o0, o1);
        *(float2*)&g_po[((size_t)grp * NHEAD_ + head) * D_ + pvd2 * 2] =
            make_float2(o0, o1);
    }
    if (t < 4) {
        int head = bkv * 4 + t;
        g_pml[(grp * NHEAD_ + head) * 2 + 0] = Msm[t];
        g_pml[(grp * NHEAD_ + head) * 2 + 1] = Lsm[t];
    }
}

// ---------------- combine partials -> bf16 hi/lo attout ----------------
__global__ void combine_kernel()
{
    const int head = blockIdx.x;
    const int t    = threadIdx.x;

    float M = -1e30f;
#pragma unroll
    for (int c = 0; c < NCHG_; c++)
        M = fmaxf(M, g_pml[(c * NHEAD_ + head) * 2]);

    float denom = 0.f, acc = 0.f;
#pragma unroll
    for (int c = 0; c < NCHG_; c++) {
        float m = g_pml[(c * NHEAD_ + head) * 2 + 0];
        float l = g_pml[(c * NHEAD_ + head) * 2 + 1];
        float w = __expf(m - M);
        denom += w * l;
        acc = fmaf(w, g_po[((size_t)c * NHEAD_ + head) * D_ + t], acc);
    }
    float r = acc / denom;
    // attout[b][h*128+d] at flat index head*128 + t  (b-major == m-major)
    __nv_bfloat16 hh = __float2bfloat16(r);
    g_ahi[head * 128 + t] = __bfloat16_as_ushort(hh);
    g_alo[head * 128 + t] =
        __bfloat16_as_ushort(__float2bfloat16(r - __bfloat162float(hh)));
}

// ====================================================================
extern "C" void kernel_launch(void* const* d_in, const int* in_sizes, int n_in,
                              void* d_out, int out_size)
{
    const float* x    = (const float*)d_in[0];
    const float* wqkv = (const float*)d_in[1];
    const float* wo   = (const float*)d_in[2];
    const float* rot  = (const float*)d_in[3];
    const float* ck   = (const float*)d_in[4];
    const float* cv   = (const float*)d_in[5];
    float* out = (float*)d_out;

    static int smem_set = 0;
    if (!smem_set) {
        cudaFuncSetAttribute(attn_group,
                             cudaFuncAttributeMaxDynamicSharedMemorySize,
                             ATT_SMEM_);
        cudaFuncSetAttribute(gemm_mma,
                             cudaFuncAttributeMaxDynamicSharedMemorySize,
                             GSMEM_);
        smem_set = 1;
    }

    // 0) X -> bf16 hi/lo
    convx<<<512, 256>>>(x);

    // 1) QKV projection: mma.sync bf16x3, split-K 8
    gemm_mma<<<dim3(48, SPLITS_), 256, GSMEM_>>>(wqkv, QKVD_, 0);

    // 2) RoPE with fused split-K reduction
    rope_kernel<<<1280, 128>>>(rot);

    // 3) pipelined flash-decode attention (8 groups x 8 chunks x 32 keys)
    attn_group<<<dim3(NBKV_, NCHG_), 256, ATT_SMEM_>>>(ck, cv);
    combine_kernel<<<NHEAD_, 128>>>();

    // 4) output projection: mma.sync bf16x3 + reduce into d_out
    gemm_mma<<<dim3(32, SPLITS_), 256, GSMEM_>>>(wo, HID_, 1);
    reduce_part<<<512, 256>>>(out, B_ * HID_);
}